// round 9
// baseline (speedup 1.0000x reference)
#include <cuda_runtime.h>
#include <cstdint>

// Embedding backward (scatter-add): 3-chunk L2-resident pipeline with the
// next chunk's zeroing FUSED into the current chunk's scatter kernel.
//   d_in[0]: grad_output, float32, [B*S, 128]   (B*S = 131072)
//   d_in[1]: indices,     int32,   [B*S]
//   d_out  : float32 [200000, 128]; segment_sum skipping index==0.
//
// Pipeline:  zero(c0) -> [scatter(c0) + zero(c1)] -> [scatter(c1) + zero(c2)]
//            -> scatter(c2)
// Concurrent L2 footprint = 2 chunks = ~68 MB < 126 MB L2, so atomics always
// RMW freshly-zeroed L2-resident lines (no DRAM read-allocate; R5-verified),
// and the zero work rides in the scatter kernel's BW/issue slack.

static constexpr int D   = 128;
static constexpr int D4  = D / 4;      // 32 float4 per row = one warp
static constexpr int RPW = 8;          // rows per warp (MLP-8 grad loads)
static constexpr int NUM_CHUNKS = 3;   // ~34 MB per chunk

// ---------------------------------------------------------------------------
// Standalone zero (for chunk 0 only).
// ---------------------------------------------------------------------------
__global__ void __launch_bounds__(256) zero_chunk_kernel(float4* __restrict__ out,
                                                         long long f4_lo,
                                                         long long f4_hi) {
    long long i = f4_lo + (long long)blockIdx.x * blockDim.x + threadIdx.x;
    if (i < f4_hi) out[i] = make_float4(0.f, 0.f, 0.f, 0.f);
}

// ---------------------------------------------------------------------------
// Fused kernel: CTAs [0, scatter_blocks) scatter chunk [row_lo, row_hi);
// CTAs [scatter_blocks, ...) zero float4s [zf4_lo, zf4_hi) (next chunk).
// ---------------------------------------------------------------------------
__global__ void __launch_bounds__(256) scatter_plus_zero_kernel(
    const float4* __restrict__ grad,   // [rows, 32] as float4
    const int* __restrict__ indices,   // [rows]
    float* __restrict__ out,           // [V, 128]
    int rows, int row_lo, int row_hi,
    int scatter_blocks,
    long long zf4_lo, long long zf4_hi)
{
    if ((int)blockIdx.x >= scatter_blocks) {
        // ---- zero segment: next chunk, normal write-allocate stores ----
        long long zb = (long long)(blockIdx.x - scatter_blocks);
        long long i = zf4_lo + zb * blockDim.x + threadIdx.x;
        if (i < zf4_hi)
            reinterpret_cast<float4*>(out)[i] = make_float4(0.f, 0.f, 0.f, 0.f);
        return;
    }

    // ---- scatter segment: warp owns RPW consecutive rows ----
    int warp = (blockIdx.x * blockDim.x + threadIdx.x) >> 5;
    int lane = threadIdx.x & 31;
    int base = warp * RPW;
    if (base >= rows) return;

    int e[RPW];
    if (base + RPW <= rows) {
        int4 ia = __ldg(reinterpret_cast<const int4*>(indices) + warp * 2);
        int4 ib = __ldg(reinterpret_cast<const int4*>(indices) + warp * 2 + 1);
        e[0]=ia.x; e[1]=ia.y; e[2]=ia.z; e[3]=ia.w;
        e[4]=ib.x; e[5]=ib.y; e[6]=ib.z; e[7]=ib.w;
    } else {
        #pragma unroll
        for (int j = 0; j < RPW; ++j)
            e[j] = (base + j < rows) ? __ldg(&indices[base + j]) : 0;
    }

    // Up to 8 independent evict-first grad loads in flight.
    bool   v[RPW];
    float4 g[RPW];
    #pragma unroll
    for (int j = 0; j < RPW; ++j) {
        v[j] = (e[j] != 0) & (e[j] >= row_lo) & (e[j] < row_hi);
        if (v[j])
            g[j] = __ldcs(&grad[(long long)(base + j) * D4 + lane]);
    }

    #pragma unroll
    for (int j = 0; j < RPW; ++j) {
        if (v[j]) {
            float* dst = out + (long long)e[j] * D + lane * 4;
            asm volatile(
                "red.global.add.v4.f32 [%0], {%1, %2, %3, %4};"
                :
                : "l"(dst), "f"(g[j].x), "f"(g[j].y), "f"(g[j].z), "f"(g[j].w)
                : "memory");
        }
    }
}

// ---------------------------------------------------------------------------
extern "C" void kernel_launch(void* const* d_in, const int* in_sizes, int n_in,
                              void* d_out, int out_size) {
    const float4* grad = (const float4*)d_in[0];
    const int* indices = (const int*)d_in[1];
    float* out         = (float*)d_out;

    const int rows = in_sizes[1];                 // B*S = 131072
    const long long V = (long long)out_size / D;  // table rows = 200000

    const int threads = 256;
    const int scatter_blocks =
        (rows + (threads / 32) * RPW - 1) / ((threads / 32) * RPW);  // 2048

    long long rows_per_chunk = (V + NUM_CHUNKS - 1) / NUM_CHUNKS;

    // Chunk boundaries (rows)
    auto chunk_lo = [&](int c) {
        long long lo = (long long)c * rows_per_chunk;
        return lo > V ? V : lo;
    };
    auto chunk_hi = [&](int c) {
        long long hi = (long long)(c + 1) * rows_per_chunk;
        return hi > V ? V : hi;
    };

    // Zero chunk 0 standalone.
    {
        long long f4_lo = chunk_lo(0) * D4;
        long long f4_hi = chunk_hi(0) * D4;
        long long n = f4_hi - f4_lo;
        int zb = (int)((n + threads - 1) / threads);
        if (zb > 0) zero_chunk_kernel<<<zb, threads>>>((float4*)out, f4_lo, f4_hi);
    }

    // For each chunk c: scatter(c) fused with zero(c+1).
    for (int c = 0; c < NUM_CHUNKS; ++c) {
        long long lo = chunk_lo(c), hi = chunk_hi(c);
        if (lo >= hi) break;

        long long zf4_lo = 0, zf4_hi = 0;
        int zero_blocks = 0;
        if (c + 1 < NUM_CHUNKS) {
            zf4_lo = chunk_lo(c + 1) * D4;
            zf4_hi = chunk_hi(c + 1) * D4;
            long long zn = zf4_hi - zf4_lo;
            zero_blocks = (int)((zn + threads - 1) / threads);
        }

        int total_blocks = scatter_blocks + zero_blocks;
        scatter_plus_zero_kernel<<<total_blocks, threads>>>(
            grad, indices, out, rows, (int)lo, (int)hi,
            scatter_blocks, zf4_lo, zf4_hi);
    }
}

// round 10
// speedup vs baseline: 1.0008x; 1.0008x over previous
#include <cuda_runtime.h>
#include <cstdint>

// Embedding backward (scatter-add): 3-chunk L2-resident pipeline with the
// next chunk's zeroing FUSED into the current chunk's scatter kernel.
//   d_in[0]: grad_output, float32, [B*S, 128]   (B*S = 131072)
//   d_in[1]: indices,     int32,   [B*S]
//   d_out  : float32 [200000, 128]; segment_sum skipping index==0.
//
// Pipeline:  zero(c0) -> [scatter(c0) + zero(c1)] -> [scatter(c1) + zero(c2)]
//            -> scatter(c2)
// Concurrent L2 footprint = 2 chunks = ~68 MB < 126 MB L2, so atomics always
// RMW freshly-zeroed L2-resident lines (no DRAM read-allocate; R5-verified),
// and the zero work rides in the scatter kernel's BW/issue slack.

static constexpr int D   = 128;
static constexpr int D4  = D / 4;      // 32 float4 per row = one warp
static constexpr int RPW = 8;          // rows per warp (MLP-8 grad loads)
static constexpr int NUM_CHUNKS = 3;   // ~34 MB per chunk

// ---------------------------------------------------------------------------
// Standalone zero (for chunk 0 only).
// ---------------------------------------------------------------------------
__global__ void __launch_bounds__(256) zero_chunk_kernel(float4* __restrict__ out,
                                                         long long f4_lo,
                                                         long long f4_hi) {
    long long i = f4_lo + (long long)blockIdx.x * blockDim.x + threadIdx.x;
    if (i < f4_hi) out[i] = make_float4(0.f, 0.f, 0.f, 0.f);
}

// ---------------------------------------------------------------------------
// Fused kernel: CTAs [0, scatter_blocks) scatter chunk [row_lo, row_hi);
// CTAs [scatter_blocks, ...) zero float4s [zf4_lo, zf4_hi) (next chunk).
// ---------------------------------------------------------------------------
__global__ void __launch_bounds__(256) scatter_plus_zero_kernel(
    const float4* __restrict__ grad,   // [rows, 32] as float4
    const int* __restrict__ indices,   // [rows]
    float* __restrict__ out,           // [V, 128]
    int rows, int row_lo, int row_hi,
    int scatter_blocks,
    long long zf4_lo, long long zf4_hi)
{
    if ((int)blockIdx.x >= scatter_blocks) {
        // ---- zero segment: next chunk, normal write-allocate stores ----
        long long zb = (long long)(blockIdx.x - scatter_blocks);
        long long i = zf4_lo + zb * blockDim.x + threadIdx.x;
        if (i < zf4_hi)
            reinterpret_cast<float4*>(out)[i] = make_float4(0.f, 0.f, 0.f, 0.f);
        return;
    }

    // ---- scatter segment: warp owns RPW consecutive rows ----
    int warp = (blockIdx.x * blockDim.x + threadIdx.x) >> 5;
    int lane = threadIdx.x & 31;
    int base = warp * RPW;
    if (base >= rows) return;

    int e[RPW];
    if (base + RPW <= rows) {
        int4 ia = __ldg(reinterpret_cast<const int4*>(indices) + warp * 2);
        int4 ib = __ldg(reinterpret_cast<const int4*>(indices) + warp * 2 + 1);
        e[0]=ia.x; e[1]=ia.y; e[2]=ia.z; e[3]=ia.w;
        e[4]=ib.x; e[5]=ib.y; e[6]=ib.z; e[7]=ib.w;
    } else {
        #pragma unroll
        for (int j = 0; j < RPW; ++j)
            e[j] = (base + j < rows) ? __ldg(&indices[base + j]) : 0;
    }

    // Up to 8 independent evict-first grad loads in flight.
    bool   v[RPW];
    float4 g[RPW];
    #pragma unroll
    for (int j = 0; j < RPW; ++j) {
        v[j] = (e[j] != 0) & (e[j] >= row_lo) & (e[j] < row_hi);
        if (v[j])
            g[j] = __ldcs(&grad[(long long)(base + j) * D4 + lane]);
    }

    #pragma unroll
    for (int j = 0; j < RPW; ++j) {
        if (v[j]) {
            float* dst = out + (long long)e[j] * D + lane * 4;
            asm volatile(
                "red.global.add.v4.f32 [%0], {%1, %2, %3, %4};"
                :
                : "l"(dst), "f"(g[j].x), "f"(g[j].y), "f"(g[j].z), "f"(g[j].w)
                : "memory");
        }
    }
}

// ---------------------------------------------------------------------------
extern "C" void kernel_launch(void* const* d_in, const int* in_sizes, int n_in,
                              void* d_out, int out_size) {
    const float4* grad = (const float4*)d_in[0];
    const int* indices = (const int*)d_in[1];
    float* out         = (float*)d_out;

    const int rows = in_sizes[1];                 // B*S = 131072
    const long long V = (long long)out_size / D;  // table rows = 200000

    const int threads = 256;
    const int scatter_blocks =
        (rows + (threads / 32) * RPW - 1) / ((threads / 32) * RPW);  // 2048

    long long rows_per_chunk = (V + NUM_CHUNKS - 1) / NUM_CHUNKS;

    // Chunk boundaries (rows)
    auto chunk_lo = [&](int c) {
        long long lo = (long long)c * rows_per_chunk;
        return lo > V ? V : lo;
    };
    auto chunk_hi = [&](int c) {
        long long hi = (long long)(c + 1) * rows_per_chunk;
        return hi > V ? V : hi;
    };

    // Zero chunk 0 standalone.
    {
        long long f4_lo = chunk_lo(0) * D4;
        long long f4_hi = chunk_hi(0) * D4;
        long long n = f4_hi - f4_lo;
        int zb = (int)((n + threads - 1) / threads);
        if (zb > 0) zero_chunk_kernel<<<zb, threads>>>((float4*)out, f4_lo, f4_hi);
    }

    // For each chunk c: scatter(c) fused with zero(c+1).
    for (int c = 0; c < NUM_CHUNKS; ++c) {
        long long lo = chunk_lo(c), hi = chunk_hi(c);
        if (lo >= hi) break;

        long long zf4_lo = 0, zf4_hi = 0;
        int zero_blocks = 0;
        if (c + 1 < NUM_CHUNKS) {
            zf4_lo = chunk_lo(c + 1) * D4;
            zf4_hi = chunk_hi(c + 1) * D4;
            long long zn = zf4_hi - zf4_lo;
            zero_blocks = (int)((zn + threads - 1) / threads);
        }

        int total_blocks = scatter_blocks + zero_blocks;
        scatter_plus_zero_kernel<<<total_blocks, threads>>>(
            grad, indices, out, rows, (int)lo, (int)hi,
            scatter_blocks, zf4_lo, zf4_hi);
    }
}